// round 11
// baseline (speedup 1.0000x reference)
#include <cuda_runtime.h>
#include <math.h>

#define B 32
#define S 4096
#define H 1024
#define WARPS_PER_BLOCK 8
#define K1_THREADS (WARPS_PER_BLOCK * 32)      // 256
#define K1_BLOCKS 296                          // 2/SM on 148 SMs (<=304 on GB300's 152)
#define NWARPS (K1_BLOCKS * WARPS_PER_BLOCK)   // 2368
#define WARPS_PER_BATCH (NWARPS / B)           // 74
#define ROWS_BASE (S / WARPS_PER_BATCH)        // 55
#define ROWS_REM (S % WARPS_PER_BATCH)         // 26 (first 26 warps do 56 rows)

// Finalize work units: 128 weight-norm + 256 context-slice = 384
#define WNORM_UNITS ((B * S / 4) / K1_THREADS)   // 128
#define CSLICE_PER_BATCH 8                       // 128 floats of H each
#define TOTAL_UNITS (WNORM_UNITS + B * CSLICE_PER_BATCH)  // 384

// Scratch (__device__ globals; no dynamic allocation allowed)
__device__ float4 g_ctx_partial[NWARPS * (H / 4)];   // 9.5 MB, batch-contiguous
__device__ float  g_m_partial[NWARPS];
__device__ float  g_l_partial[NWARPS];
__device__ unsigned int g_bar;                        // epoch barrier counter

// ---------------------------------------------------------------------------
// Persistent kernel: streaming pass (proven 82.5us body) -> grid barrier ->
// distributed finalize (384 units over 296 blocks).
// ---------------------------------------------------------------------------
__global__ __launch_bounds__(K1_THREADS, 2)
void attn_persistent(const float* __restrict__ query,
                     const float* __restrict__ keys,
                     float* __restrict__ out_ctx,
                     float* __restrict__ out_weights)
{
    // ======================== Phase 1: streaming ========================
    {
        const int wg   = blockIdx.x * WARPS_PER_BLOCK + (threadIdx.x >> 5);
        const int lane = threadIdx.x & 31;
        const int b    = wg / WARPS_PER_BATCH;
        const int i    = wg % WARPS_PER_BATCH;
        const int start = i * ROWS_BASE + (i < ROWS_REM ? i : ROWS_REM);
        const int count = ROWS_BASE + (i < ROWS_REM ? 1 : 0);

        const float4* q4 = reinterpret_cast<const float4*>(query + (size_t)b * H);
        float4 qv[8];
#pragma unroll
        for (int j = 0; j < 8; ++j) qv[j] = q4[lane + 32 * j];

        float4 acc[8];
#pragma unroll
        for (int j = 0; j < 8; ++j) acc[j] = make_float4(0.f, 0.f, 0.f, 0.f);
        float m = -INFINITY;
        float l = 0.f;

        const size_t base = ((size_t)b * S + start) * H;
        float* wout = out_weights + (size_t)b * S + start;

        for (int r = 0; r < count; ++r) {
            const float4* k4 = reinterpret_cast<const float4*>(keys + base + (size_t)r * H);
            float4 kv[8];
#pragma unroll
            for (int j = 0; j < 8; ++j) kv[j] = k4[lane + 32 * j];

            float d = 0.f;
#pragma unroll
            for (int j = 0; j < 8; ++j) {
                d = fmaf(qv[j].x, kv[j].x, d);
                d = fmaf(qv[j].y, kv[j].y, d);
                d = fmaf(qv[j].z, kv[j].z, d);
                d = fmaf(qv[j].w, kv[j].w, d);
            }
#pragma unroll
            for (int o = 16; o > 0; o >>= 1)
                d += __shfl_xor_sync(0xFFFFFFFFu, d, o);

            if (lane == 0) wout[r] = d;

            float p;
            if (d > m) {                       // warp-uniform branch
                float scale = __expf(m - d);   // first iter: exp(-inf)=0
#pragma unroll
                for (int j = 0; j < 8; ++j) {
                    acc[j].x *= scale; acc[j].y *= scale;
                    acc[j].z *= scale; acc[j].w *= scale;
                }
                l = fmaf(l, scale, 1.f);
                m = d;
                p = 1.f;
            } else {
                p = __expf(d - m);
                l += p;
            }
#pragma unroll
            for (int j = 0; j < 8; ++j) {
                acc[j].x = fmaf(p, kv[j].x, acc[j].x);
                acc[j].y = fmaf(p, kv[j].y, acc[j].y);
                acc[j].z = fmaf(p, kv[j].z, acc[j].z);
                acc[j].w = fmaf(p, kv[j].w, acc[j].w);
            }
        }

        float4* dst = &g_ctx_partial[(size_t)wg * (H / 4)];
#pragma unroll
        for (int j = 0; j < 8; ++j) dst[lane + 32 * j] = acc[j];
        if (lane == 0) {
            g_m_partial[wg] = m;
            g_l_partial[wg] = l;
        }
    }

    // ======================== Grid barrier (epoch) ========================
    __syncthreads();
    if (threadIdx.x == 0) {
        __threadfence();                               // release partials
        unsigned int old = atomicAdd(&g_bar, 1u);
        unsigned int target = (old / K1_BLOCKS + 1u) * K1_BLOCKS;
        volatile unsigned int* vb = &g_bar;
        while (*vb < target) __nanosleep(128);
    }
    __syncthreads();
    __threadfence();                                   // acquire

    // ======================== Phase 2: finalize ========================
    __shared__ float sm[4], sl[4];
    __shared__ float sM, sInvL;
    __shared__ float sF[WARPS_PER_BATCH];              // per-slot factors
    __shared__ float4 sacc[8][32];

    const int t = threadIdx.x;

    for (int u = blockIdx.x; u < TOTAL_UNITS; u += K1_BLOCKS) {
        const bool is_norm = (u < WNORM_UNITS);
        const int b = is_norm ? (u >> 2) : ((u - WNORM_UNITS) >> 3);

        // --- per-unit stats over batch b's 74 (m,l) pairs (L2-hot) ---
        float mc = -INFINITY, lc = 0.f;
        if (t < WARPS_PER_BATCH) {
            const int p = b * WARPS_PER_BATCH + t;
            mc = __ldcg(&g_m_partial[p]);
            lc = __ldcg(&g_l_partial[p]);
        }
        __syncthreads();   // protect smem reuse across loop iterations
        if (t < 128) {
            float v = mc;
#pragma unroll
            for (int o = 16; o > 0; o >>= 1)
                v = fmaxf(v, __shfl_xor_sync(0xFFFFFFFFu, v, o));
            if ((t & 31) == 0) sm[t >> 5] = v;
        }
        __syncthreads();
        if (t == 0) sM = fmaxf(fmaxf(sm[0], sm[1]), fmaxf(sm[2], sm[3]));
        __syncthreads();
        const float M = sM;
        if (t < 128) {
            float s = lc * __expf(mc - M);             // idle slots add 0
#pragma unroll
            for (int o = 16; o > 0; o >>= 1)
                s += __shfl_xor_sync(0xFFFFFFFFu, s, o);
            if ((t & 31) == 0) sl[t >> 5] = s;
        }
        __syncthreads();
        if (t == 0) sInvL = 1.f / (sl[0] + sl[1] + sl[2] + sl[3]);
        __syncthreads();
        const float invL = sInvL;

        if (is_norm) {
            // normalize 256 contiguous float4 of batch b's weights
            const int idx = u * K1_THREADS + t;        // u>>2 == b
            float4 s = __ldcg(&reinterpret_cast<float4*>(out_weights)[idx]);
            s.x = __expf(s.x - M) * invL;
            s.y = __expf(s.y - M) * invL;
            s.z = __expf(s.z - M) * invL;
            s.w = __expf(s.w - M) * invL;
            reinterpret_cast<float4*>(out_weights)[idx] = s;
        } else {
            // context slice sub of batch b: sum over 74 partials
            const int sub = (u - WNORM_UNITS) & (CSLICE_PER_BATCH - 1);
            if (t < WARPS_PER_BATCH)
                sF[t] = __expf(mc - M) * invL;
            __syncthreads();

            const int f = t & 31;
            const size_t sbase = (size_t)b * WARPS_PER_BATCH * (H / 4) + sub * 32 + f;
            float4 a0 = make_float4(0.f, 0.f, 0.f, 0.f);
            float4 a1 = make_float4(0.f, 0.f, 0.f, 0.f);
            int i = (t >> 5);
            // unrolled-by-2: independent loads in flight
            for (; i + 8 < WARPS_PER_BATCH; i += 16) {
                float4 v0 = __ldcg(&g_ctx_partial[sbase + (size_t)i * (H / 4)]);
                float4 v1 = __ldcg(&g_ctx_partial[sbase + (size_t)(i + 8) * (H / 4)]);
                const float f0 = sF[i], f1 = sF[i + 8];
                a0.x = fmaf(f0, v0.x, a0.x); a0.y = fmaf(f0, v0.y, a0.y);
                a0.z = fmaf(f0, v0.z, a0.z); a0.w = fmaf(f0, v0.w, a0.w);
                a1.x = fmaf(f1, v1.x, a1.x); a1.y = fmaf(f1, v1.y, a1.y);
                a1.z = fmaf(f1, v1.z, a1.z); a1.w = fmaf(f1, v1.w, a1.w);
            }
            if (i < WARPS_PER_BATCH) {
                float4 v0 = __ldcg(&g_ctx_partial[sbase + (size_t)i * (H / 4)]);
                const float f0 = sF[i];
                a0.x = fmaf(f0, v0.x, a0.x); a0.y = fmaf(f0, v0.y, a0.y);
                a0.z = fmaf(f0, v0.z, a0.z); a0.w = fmaf(f0, v0.w, a0.w);
            }
            a0.x += a1.x; a0.y += a1.y; a0.z += a1.z; a0.w += a1.w;

            sacc[t >> 5][f] = a0;
            __syncthreads();
            if (t < 32) {
                float4 c = sacc[0][t];
#pragma unroll
                for (int g = 1; g < 8; ++g) {
                    float4 v = sacc[g][t];
                    c.x += v.x; c.y += v.y; c.z += v.z; c.w += v.w;
                }
                reinterpret_cast<float4*>(out_ctx)[b * (H / 4) + sub * 32 + t] = c;
            }
        }
        __syncthreads();
    }
}

extern "C" void kernel_launch(void* const* d_in, const int* in_sizes, int n_in,
                              void* d_out, int out_size)
{
    const float* query = (const float*)d_in[0];   // (32,1,1024)
    const float* keys  = (const float*)d_in[1];   // (32,4096,1024)
    float* out = (float*)d_out;
    float* out_ctx = out;                  // (B,H)
    float* out_w   = out + (size_t)B * H;  // (B,S)

    attn_persistent<<<K1_BLOCKS, K1_THREADS>>>(query, keys, out_ctx, out_w);
}

// round 12
// speedup vs baseline: 1.0152x; 1.0152x over previous
#include <cuda_runtime.h>
#include <math.h>

#define B 32
#define S 4096
#define H 1024
#define WARPS_PER_BLOCK 8
#define THREADS (WARPS_PER_BLOCK * 32)          // 256
#define BLOCKS_PER_BATCH 9
#define NBLOCKS (B * BLOCKS_PER_BATCH)          // 288
#define WARPS_PER_BATCH (BLOCKS_PER_BATCH * WARPS_PER_BLOCK)  // 72
// rows per warp-slot: slots 0..63 get 57 rows, slots 64..71 get 56
#define ROWS_LO 57
#define ROWS_HI_START 64

// Scratch (__device__ globals; no dynamic allocation allowed)
__device__ float4 g_ctx_partial[B * WARPS_PER_BATCH * (H / 4)];  // 9.4 MB
__device__ float  g_m_partial[B * WARPS_PER_BATCH];
__device__ float  g_l_partial[B * WARPS_PER_BATCH];
__device__ unsigned int g_cnt[B];        // per-batch arrival counters (epoch via %9)

// ---------------------------------------------------------------------------
// One kernel. Phase 1: proven streaming body (q/kv/acc in regs, 2 blocks/SM).
// Phase 2: the 9th-arriving block of each batch finalizes that batch alone,
// overlapping finalize with other batches' streaming stragglers.
// ---------------------------------------------------------------------------
__global__ __launch_bounds__(THREADS, 2)
void attn_fused(const float* __restrict__ query,
                const float* __restrict__ keys,
                float* __restrict__ out_ctx,
                float* __restrict__ out_weights)
{
    const int w    = threadIdx.x >> 5;
    const int lane = threadIdx.x & 31;
    const int b    = blockIdx.x / BLOCKS_PER_BATCH;
    const int jblk = blockIdx.x % BLOCKS_PER_BATCH;
    const int i    = jblk * WARPS_PER_BLOCK + w;        // slot 0..71
    const int start = i * 56 + (i < ROWS_HI_START ? i : ROWS_HI_START);
    const int count = (i < ROWS_HI_START) ? ROWS_LO : 56;

    // ======================== Phase 1: streaming ========================
    {
        const float4* q4 = reinterpret_cast<const float4*>(query + (size_t)b * H);
        float4 qv[8];
#pragma unroll
        for (int j = 0; j < 8; ++j) qv[j] = q4[lane + 32 * j];

        float4 acc[8];
#pragma unroll
        for (int j = 0; j < 8; ++j) acc[j] = make_float4(0.f, 0.f, 0.f, 0.f);
        float m = -INFINITY;
        float l = 0.f;

        const size_t base = ((size_t)b * S + start) * H;
        float* wout = out_weights + (size_t)b * S + start;

        for (int r = 0; r < count; ++r) {
            const float4* k4 = reinterpret_cast<const float4*>(keys + base + (size_t)r * H);
            float4 kv[8];
#pragma unroll
            for (int j = 0; j < 8; ++j) kv[j] = k4[lane + 32 * j];

            float d = 0.f;
#pragma unroll
            for (int j = 0; j < 8; ++j) {
                d = fmaf(qv[j].x, kv[j].x, d);
                d = fmaf(qv[j].y, kv[j].y, d);
                d = fmaf(qv[j].z, kv[j].z, d);
                d = fmaf(qv[j].w, kv[j].w, d);
            }
#pragma unroll
            for (int o = 16; o > 0; o >>= 1)
                d += __shfl_xor_sync(0xFFFFFFFFu, d, o);

            if (lane == 0) wout[r] = d;

            float p;
            if (d > m) {                       // warp-uniform branch
                float scale = __expf(m - d);   // first iter: exp(-inf)=0
#pragma unroll
                for (int j = 0; j < 8; ++j) {
                    acc[j].x *= scale; acc[j].y *= scale;
                    acc[j].z *= scale; acc[j].w *= scale;
                }
                l = fmaf(l, scale, 1.f);
                m = d;
                p = 1.f;
            } else {
                p = __expf(d - m);
                l += p;
            }
#pragma unroll
            for (int j = 0; j < 8; ++j) {
                acc[j].x = fmaf(p, kv[j].x, acc[j].x);
                acc[j].y = fmaf(p, kv[j].y, acc[j].y);
                acc[j].z = fmaf(p, kv[j].z, acc[j].z);
                acc[j].w = fmaf(p, kv[j].w, acc[j].w);
            }
        }

        const int slot = b * WARPS_PER_BATCH + i;
        float4* dst = &g_ctx_partial[(size_t)slot * (H / 4)];
#pragma unroll
        for (int j = 0; j < 8; ++j) dst[lane + 32 * j] = acc[j];
        if (lane == 0) {
            g_m_partial[slot] = m;
            g_l_partial[slot] = l;
        }
    }

    // =============== arrival: am I the last block of batch b? ===============
    __shared__ unsigned int s_last;
    __syncthreads();
    if (threadIdx.x == 0) {
        __threadfence();                                 // release my partials
        unsigned int old = atomicAdd(&g_cnt[b], 1u);
        s_last = ((old % BLOCKS_PER_BATCH) == (BLOCKS_PER_BATCH - 1)) ? 1u : 0u;
    }
    __syncthreads();
    if (!s_last) return;
    __threadfence();                                     // acquire peers' partials

    // ======================== Phase 2: finalize batch b ========================
    const int t = threadIdx.x;
    __shared__ float sm[4], sl[4];
    __shared__ float sM, sInvL;
    __shared__ float sF[WARPS_PER_BATCH];

    float mc = -INFINITY, lc = 0.f;
    if (t < WARPS_PER_BATCH) {
        const int p = b * WARPS_PER_BATCH + t;
        mc = __ldcg(&g_m_partial[p]);
        lc = __ldcg(&g_l_partial[p]);
    }
    if (t < 128) {
        float v = mc;
#pragma unroll
        for (int o = 16; o > 0; o >>= 1)
            v = fmaxf(v, __shfl_xor_sync(0xFFFFFFFFu, v, o));
        if ((t & 31) == 0) sm[t >> 5] = v;
    }
    __syncthreads();
    if (t == 0) sM = fmaxf(fmaxf(sm[0], sm[1]), fmaxf(sm[2], sm[3]));
    __syncthreads();
    const float M = sM;
    if (t < 128) {
        float s = lc * __expf(mc - M);                   // idle slots add 0
#pragma unroll
        for (int o = 16; o > 0; o >>= 1)
            s += __shfl_xor_sync(0xFFFFFFFFu, s, o);
        if ((t & 31) == 0) sl[t >> 5] = s;
    }
    __syncthreads();
    if (t == 0) sInvL = 1.f / (sl[0] + sl[1] + sl[2] + sl[3]);
    __syncthreads();
    const float invL = sInvL;
    if (t < WARPS_PER_BATCH) sF[t] = __expf(mc - M) * invL;
    __syncthreads();

    // --- normalize weights of batch b: 1024 float4, 4 per thread ---
    {
        float4* wv = reinterpret_cast<float4*>(out_weights + (size_t)b * S);
#pragma unroll
        for (int k = 0; k < 4; ++k) {
            const int idx = t + 256 * k;
            float4 s = __ldcg(&wv[idx]);
            s.x = __expf(s.x - M) * invL;
            s.y = __expf(s.y - M) * invL;
            s.z = __expf(s.z - M) * invL;
            s.w = __expf(s.w - M) * invL;
            wv[idx] = s;
        }
    }

    // --- combine context: thread t owns float4 element t (256 of H/4) ---
    {
        const size_t pbase = (size_t)b * WARPS_PER_BATCH * (H / 4) + t;
        float4 a0 = make_float4(0.f, 0.f, 0.f, 0.f);
        float4 a1 = make_float4(0.f, 0.f, 0.f, 0.f);
        float4 a2 = make_float4(0.f, 0.f, 0.f, 0.f);
        float4 a3 = make_float4(0.f, 0.f, 0.f, 0.f);
#pragma unroll
        for (int i4 = 0; i4 < WARPS_PER_BATCH; i4 += 4) {   // 72 = 18*4
            float4 v0 = __ldcg(&g_ctx_partial[pbase + (size_t)(i4 + 0) * (H / 4)]);
            float4 v1 = __ldcg(&g_ctx_partial[pbase + (size_t)(i4 + 1) * (H / 4)]);
            float4 v2 = __ldcg(&g_ctx_partial[pbase + (size_t)(i4 + 2) * (H / 4)]);
            float4 v3 = __ldcg(&g_ctx_partial[pbase + (size_t)(i4 + 3) * (H / 4)]);
            const float f0 = sF[i4 + 0], f1 = sF[i4 + 1];
            const float f2 = sF[i4 + 2], f3 = sF[i4 + 3];
            a0.x = fmaf(f0, v0.x, a0.x); a0.y = fmaf(f0, v0.y, a0.y);
            a0.z = fmaf(f0, v0.z, a0.z); a0.w = fmaf(f0, v0.w, a0.w);
            a1.x = fmaf(f1, v1.x, a1.x); a1.y = fmaf(f1, v1.y, a1.y);
            a1.z = fmaf(f1, v1.z, a1.z); a1.w = fmaf(f1, v1.w, a1.w);
            a2.x = fmaf(f2, v2.x, a2.x); a2.y = fmaf(f2, v2.y, a2.y);
            a2.z = fmaf(f2, v2.z, a2.z); a2.w = fmaf(f2, v2.w, a2.w);
            a3.x = fmaf(f3, v3.x, a3.x); a3.y = fmaf(f3, v3.y, a3.y);
            a3.z = fmaf(f3, v3.z, a3.z); a3.w = fmaf(f3, v3.w, a3.w);
        }
        a0.x += a1.x + a2.x + a3.x;
        a0.y += a1.y + a2.y + a3.y;
        a0.z += a1.z + a2.z + a3.z;
        a0.w += a1.w + a2.w + a3.w;
        reinterpret_cast<float4*>(out_ctx)[b * (H / 4) + t] = a0;
    }
}

extern "C" void kernel_launch(void* const* d_in, const int* in_sizes, int n_in,
                              void* d_out, int out_size)
{
    const float* query = (const float*)d_in[0];   // (32,1,1024)
    const float* keys  = (const float*)d_in[1];   // (32,4096,1024)
    float* out = (float*)d_out;
    float* out_ctx = out;                  // (B,H)
    float* out_w   = out + (size_t)B * H;  // (B,S)

    attn_fused<<<NBLOCKS, THREADS>>>(query, keys, out_ctx, out_w);
}